// round 15
// baseline (speedup 1.0000x reference)
#include <cuda_runtime.h>
#include <cuda_bf16.h>
#include <stdint.h>

#define NNODES 8192
#define DIM    256
#define ALPHA  3.0f
#define NEG    0.2f

#define TPB   256                // softmax threads per block
#define RPB   4                  // rows per softmax block
#define NWARP (TPB / 32)

// Scratch (__device__ globals; no cudaMalloc allowed)
__device__ float g_s1[NNODES];
__device__ float g_s2p[NNODES];  // permuted: g_s2p[idx[j]] = s2[j]

// Single-op hardware tanh (sm_75+): MUFU.TANH, rel err ~2^-11 (<< 1e-3 budget)
__device__ __forceinline__ float htanh(float x) {
    float y;
    asm("tanh.approx.f32 %0, %1;" : "=f"(y) : "f"(x));
    return y;
}

// ---------------------------------------------------------------------------
// score: HALF-WARP per node (16 lanes x 16 dims each) — R9 proven form.
// ---------------------------------------------------------------------------
__global__ void __launch_bounds__(128)
score_kernel(const int* __restrict__ idx,
             const float* __restrict__ e1,
             const float* __restrict__ e2,
             const float* __restrict__ w)
{
    const int node = (blockIdx.x * 128 + threadIdx.x) >> 4;
    const int sub  = threadIdx.x & 15;
    const int src  = __ldg(&idx[node]);

    const float4* r1 = (const float4*)(e1 + (size_t)src * DIM);
    const float4* r2 = (const float4*)(e2 + (size_t)src * DIM);
    const float4* w1 = (const float4*)(w);
    const float4* w2 = (const float4*)(w + DIM);

    float p1 = 0.f, p2 = 0.f;
    #pragma unroll
    for (int q = 0; q < 4; q++) {
        const int k = sub + 16 * q;                 // interleaved -> coalesced
        float4 a  = r1[k];
        float4 b  = r2[k];
        float4 wa = __ldg(&w1[k]);
        float4 wb = __ldg(&w2[k]);
        p1 += htanh(ALPHA * a.x) * wa.x + htanh(ALPHA * a.y) * wa.y
            + htanh(ALPHA * a.z) * wa.z + htanh(ALPHA * a.w) * wa.w;
        p2 += htanh(ALPHA * b.x) * wb.x + htanh(ALPHA * b.y) * wb.y
            + htanh(ALPHA * b.z) * wb.z + htanh(ALPHA * b.w) * wb.w;
    }
    #pragma unroll
    for (int o = 8; o > 0; o >>= 1) {
        p1 += __shfl_xor_sync(0xffffffffu, p1, o);
        p2 += __shfl_xor_sync(0xffffffffu, p2, o);
    }
    if (sub == 0) {
        g_s1[node] = p1;
        g_s2p[src] = p2;
    }
}

// ---------------------------------------------------------------------------
// softmax: 4 rows per block (grid 2048). s2p staged to SMEM once per block
// (LDG traffic /4); both passes read via LDS. exp recomputed in pass 2
// (MUFU is throughput-trivial — measured). Stores: contiguous STG.128.
// ---------------------------------------------------------------------------
__global__ void __launch_bounds__(TPB)
softmax_kernel(const float* __restrict__ att_b,
               float* __restrict__ out)
{
    __shared__ float  s2s[NNODES];          // 32 KB staged s2p
    __shared__ float  red[RPB][NWARP];      // per-warp partial sums

    const int t  = threadIdx.x;
    const int r0 = blockIdx.x * RPB;

    // pre-dependency prologue
    const float bias = __ldg(att_b);
    float4* s2s4 = (float4*)s2s;

    // wait for score_kernel completion (PDL)
    cudaGridDependencySynchronize();

    // stage s2p -> SMEM (one 32KB cooperative load per block)
    const float4* s2p4 = (const float4*)g_s2p;
    #pragma unroll
    for (int q = 0; q < 8; q++)
        s2s4[q * TPB + t] = __ldg(&s2p4[q * TPB + t]);

    float base[RPB];
    #pragma unroll
    for (int r = 0; r < RPB; r++)
        base[r] = g_s1[r0 + r] + bias;
    __syncthreads();

    // pass 1: per-row sums of exp(leaky(base_r + s2))
    float ps[RPB] = {0.f, 0.f, 0.f, 0.f};
    #pragma unroll
    for (int q = 0; q < 8; q++) {
        float4 s = s2s4[q * TPB + t];
        #pragma unroll
        for (int u = 0; u < 4; u++) {
            const float sv = ((const float*)&s)[u];
            #pragma unroll
            for (int r = 0; r < RPB; r++) {
                float x = base[r] + sv;
                x = (x > 0.f) ? x : NEG * x;
                ps[r] += __expf(x);
            }
        }
    }

    // joint block reduction of 4 sums
    #pragma unroll
    for (int o = 16; o > 0; o >>= 1) {
        #pragma unroll
        for (int r = 0; r < RPB; r++)
            ps[r] += __shfl_xor_sync(0xffffffffu, ps[r], o);
    }
    if ((t & 31) == 0) {
        #pragma unroll
        for (int r = 0; r < RPB; r++)
            red[r][t >> 5] = ps[r];
    }
    __syncthreads();
    float inv[RPB];
    #pragma unroll
    for (int r = 0; r < RPB; r++) {
        float s = 0.f;
        #pragma unroll
        for (int wg = 0; wg < NWARP; wg++) s += red[r][wg];
        inv[r] = __frcp_rn(s);
    }

    // pass 2: recompute exp, scale, store 4 rows (contiguous STG.128 each)
    #pragma unroll
    for (int q = 0; q < 8; q++) {
        float4 s = s2s4[q * TPB + t];
        #pragma unroll
        for (int r = 0; r < RPB; r++) {
            float4 v;
            #pragma unroll
            for (int u = 0; u < 4; u++) {
                float x = base[r] + ((const float*)&s)[u];
                x = (x > 0.f) ? x : NEG * x;
                ((float*)&v)[u] = __expf(x) * inv[r];
            }
            ((float4*)(out + (size_t)(r0 + r) * NNODES))[q * TPB + t] = v;
        }
    }
}

// ---------------------------------------------------------------------------
// Inputs: idx[int32 N], emb1_w[f32 N*D], emb2_w[f32 N*D], att_w[f32 2D],
//         att_b[f32 1].  Output: f32 N*N.
// ---------------------------------------------------------------------------
extern "C" void kernel_launch(void* const* d_in, const int* in_sizes, int n_in,
                              void* d_out, int out_size)
{
    const int*   idx  = (const int*)  d_in[0];
    const float* e1   = (const float*)d_in[1];
    const float* e2   = (const float*)d_in[2];
    const float* attw = (const float*)d_in[3];
    const float* attb = (const float*)d_in[4];
    float*       out  = (float*)d_out;

    score_kernel<<<NNODES * 16 / 128, 128>>>(idx, e1, e2, attw);

    // Programmatic dependent launch (measured +0.35us vs plain)
    cudaLaunchConfig_t cfg = {};
    cfg.gridDim  = dim3(NNODES / RPB, 1, 1);
    cfg.blockDim = dim3(TPB, 1, 1);
    cfg.dynamicSmemBytes = 0;
    cudaLaunchAttribute attr[1];
    attr[0].id = cudaLaunchAttributeProgrammaticStreamSerialization;
    attr[0].val.programmaticStreamSerializationAllowed = 1;
    cfg.attrs    = attr;
    cfg.numAttrs = 1;
    cudaError_t err = cudaLaunchKernelEx(&cfg, softmax_kernel, attb, out);
    if (err != cudaSuccess) {
        softmax_kernel<<<NNODES / RPB, TPB>>>(attb, out);
    }
}